// round 7
// baseline (speedup 1.0000x reference)
#include <cuda_runtime.h>
#include <cuda_bf16.h>
#include <cstdint>

#define NN 4096
#define FD 256
#define BB 8

// ---------------- scratch (__device__ globals; no allocs allowed) ----------
__device__ __nv_bfloat16 g_An[(size_t)NN * NN];          // 32MB relu(sym(A)) bf16
__device__ __nv_bfloat16 g_Bt[(size_t)BB * FD * NN];     // 16MB (d_m*HW)^T rows c=b*256+o
__device__ __nv_bfloat16 g_Hhi[(size_t)BB * NN * FD];    // 16MB H hi split
__device__ __nv_bfloat16 g_Hlo[(size_t)BB * NN * FD];    // 16MB H lo split
__device__ __nv_bfloat16 g_Wht[FD * FD];                 // W^T hi  [o][k]
__device__ __nv_bfloat16 g_Wlt[FD * FD];                 // W^T lo  [o][k]
__device__ float g_HW[(size_t)BB * NN * FD];             // 32MB H@W fp32
__device__ float g_dinv[NN];
__device__ float g_Dpart[(size_t)NN * 128];              // deterministic row partials

// ---------------- PTX helpers (sm_80-era only: cp.async/ldmatrix/mma) ------
__device__ __forceinline__ uint32_t s2u(const void* p) {
    uint32_t a;
    asm("{ .reg .u64 t; cvta.to.shared.u64 t, %1; cvt.u32.u64 %0, t; }" : "=r"(a) : "l"(p));
    return a;
}

#define CPA16(dst, src) \
    asm volatile("cp.async.cg.shared.global [%0], [%1], 16;\n" :: "r"(dst), "l"(src))
#define CPA_COMMIT() asm volatile("cp.async.commit_group;\n" ::: "memory")
#define CPA_WAIT0()  asm volatile("cp.async.wait_group 0;\n" ::: "memory")
#define CPA_WAIT1()  asm volatile("cp.async.wait_group 1;\n" ::: "memory")

__device__ __forceinline__ void ldm_x4(uint32_t (&r)[4], uint32_t addr) {
    asm volatile("ldmatrix.sync.aligned.m8n8.x4.shared.b16 {%0,%1,%2,%3}, [%4];"
                 : "=r"(r[0]), "=r"(r[1]), "=r"(r[2]), "=r"(r[3]) : "r"(addr));
}

__device__ __forceinline__ void mma_bf16(float (&c)[4], const uint32_t (&a)[4],
                                         uint32_t b0, uint32_t b1) {
    asm volatile(
        "mma.sync.aligned.m16n8k16.row.col.f32.bf16.bf16.f32 "
        "{%0,%1,%2,%3}, {%4,%5,%6,%7}, {%8,%9}, {%0,%1,%2,%3};"
        : "+f"(c[0]), "+f"(c[1]), "+f"(c[2]), "+f"(c[3])
        : "r"(a[0]), "r"(a[1]), "r"(a[2]), "r"(a[3]), "r"(b0), "r"(b1));
}

#define TSTRIDE 80
#define TILE_SZ (128 * TSTRIDE)    // 10240 B per 128x32 bf16 tile
#define BTILE_SZ (256 * TSTRIDE)   // 20480 B per 256x32 bf16 tile

// ---------------- launch 1: triangular anorm + partial row sums -------------
__global__ void anorm_k(const float* __restrict__ A) {
    int bj = blockIdx.x, bi = blockIdx.y;
    if (bj < bi) return;                    // upper-triangular blocks only
    __shared__ float tA[32][33], tB[32][33];
    int i0 = bi * 32, j0 = bj * 32;
    int tx = threadIdx.x, ty = threadIdx.y;  // 32 x 8
    for (int r = ty; r < 32; r += 8) {
        tA[r][tx] = A[(size_t)(i0 + r) * NN + j0 + tx];
        tB[r][tx] = A[(size_t)(j0 + r) * NN + i0 + tx];
    }
    __syncthreads();
    for (int r = ty; r < 32; r += 8) {
        float v = 0.5f * (tA[r][tx] + tB[tx][r]);
        v = v > 0.f ? v : 0.f;
        g_An[(size_t)(i0 + r) * NN + j0 + tx] = __float2bfloat16(v);
        float s = v;
#pragma unroll
        for (int o = 16; o; o >>= 1) s += __shfl_xor_sync(0xFFFFFFFFu, s, o);
        if (tx == 0) g_Dpart[(size_t)(i0 + r) * 128 + bj] = s;
    }
    if (bi != bj) {
        for (int r = ty; r < 32; r += 8) {
            float v = 0.5f * (tB[r][tx] + tA[tx][r]);
            v = v > 0.f ? v : 0.f;
            g_An[(size_t)(j0 + r) * NN + i0 + tx] = __float2bfloat16(v);
            float s = v;
#pragma unroll
            for (int o = 16; o; o >>= 1) s += __shfl_xor_sync(0xFFFFFFFFu, s, o);
            if (tx == 0) g_Dpart[(size_t)(j0 + r) * 128 + bi] = s;
        }
    }
}

// ---------------- launch 2: fused split_h + split_wt + dinv -----------------
__global__ void fused_prep(const float* __restrict__ H, const float* __restrict__ W) {
    int blk = blockIdx.x, tid = threadIdx.x;
    if (blk < 8192) {                        // --- H hi/lo split (float4) ---
        size_t i = ((size_t)blk * 256 + tid) * 4;
        float4 v = *(const float4*)(H + i);
        __nv_bfloat16 h0 = __float2bfloat16(v.x), h1 = __float2bfloat16(v.y);
        __nv_bfloat16 h2 = __float2bfloat16(v.z), h3 = __float2bfloat16(v.w);
        __nv_bfloat16 l0 = __float2bfloat16(v.x - __bfloat162float(h0));
        __nv_bfloat16 l1 = __float2bfloat16(v.y - __bfloat162float(h1));
        __nv_bfloat16 l2 = __float2bfloat16(v.z - __bfloat162float(h2));
        __nv_bfloat16 l3 = __float2bfloat16(v.w - __bfloat162float(h3));
        __nv_bfloat162* hi = (__nv_bfloat162*)(g_Hhi + i);
        __nv_bfloat162* lo = (__nv_bfloat162*)(g_Hlo + i);
        hi[0] = __nv_bfloat162(h0, h1); hi[1] = __nv_bfloat162(h2, h3);
        lo[0] = __nv_bfloat162(l0, l1); lo[1] = __nv_bfloat162(l2, l3);
    } else if (blk < 8256) {                 // --- W^T hi/lo split ---
        __shared__ float t[32][33];
        int tI = blk - 8192;
        int o0 = (tI & 7) * 32, k0 = (tI >> 3) * 32;
        for (int i = tid; i < 1024; i += 256) {
            int r = i >> 5, c = i & 31;
            t[r][c] = W[(size_t)(k0 + r) * FD + o0 + c];
        }
        __syncthreads();
        for (int i = tid; i < 1024; i += 256) {
            int r = i >> 5, c = i & 31;
            float v = t[c][r];               // W[k0+c][o0+r]
            __nv_bfloat16 hi = __float2bfloat16(v);
            size_t idx = (size_t)(o0 + r) * FD + k0 + c;
            g_Wht[idx] = hi;
            g_Wlt[idx] = __float2bfloat16(v - __bfloat162float(hi));
        }
    } else {                                 // --- dinv from partials ---
        int row = (blk - 8256) * 256 + tid;
        const float* p = g_Dpart + (size_t)row * 128;
        float s = 0.f;
#pragma unroll 8
        for (int j = 0; j < 128; j++) s += p[j];
        g_dinv[row] = (s > 0.f) ? rsqrtf(s) : 0.f;
    }
}

// ---------------- launch 3: HW = H@W (3-pass bf16 split via mma.sync) -------
static constexpr int HW_STAGE = 4 * TILE_SZ;          // Ahi,Alo,Bhi,Blo
static constexpr int SMEM_HW  = 2 * HW_STAGE;         // 81920 (>= 128*129*4 epi)

__global__ __launch_bounds__(256, 1) void hw_gemm_mma() {
    extern __shared__ char smem[];
    uint32_t sb = s2u(smem);
    int tid = threadIdx.x, lane = tid & 31, wid = tid >> 5;
    int wm = wid >> 1, wn = wid & 1;
    int o0 = blockIdx.x * 128;
    int r0 = blockIdx.y * 128;

    const char* Ahg = (const char*)g_Hhi + (size_t)r0 * (FD * 2);
    const char* Alg = (const char*)g_Hlo + (size_t)r0 * (FD * 2);
    const char* Bhg = (const char*)g_Wht + (size_t)o0 * (FD * 2);
    const char* Blg = (const char*)g_Wlt + (size_t)o0 * (FD * 2);

    auto load = [&](int kt, int s) {
        uint32_t base = sb + s * HW_STAGE;
        size_t gk = (size_t)kt * 64;
#pragma unroll
        for (int h = 0; h < 2; h++) {
            int id = tid + h * 256;
            int r = id >> 2, c = id & 3;
            uint32_t so = r * TSTRIDE + c * 16;
            size_t go = (size_t)r * (FD * 2) + gk + c * 16;
            CPA16(base + so,               Ahg + go);
            CPA16(base + TILE_SZ + so,     Alg + go);
            CPA16(base + 2 * TILE_SZ + so, Bhg + go);
            CPA16(base + 3 * TILE_SZ + so, Blg + go);
        }
        CPA_COMMIT();
    };

    float acc[2][8][4];
#pragma unroll
    for (int i = 0; i < 2; i++)
#pragma unroll
        for (int j = 0; j < 8; j++)
#pragma unroll
            for (int v = 0; v < 4; v++) acc[i][j][v] = 0.f;

    int grp = lane >> 3, lr = lane & 7;
    int arow = wm * 32 + (grp & 1) * 8 + lr;
    int brow = wn * 64 + (grp & 1) * 8 + lr;
    int koff = (grp >> 1) * 16;

    load(0, 0);
    for (int kt = 0; kt < 8; kt++) {
        int s = kt & 1;
        if (kt + 1 < 8) { load(kt + 1, (kt + 1) & 1); CPA_WAIT1(); }
        else CPA_WAIT0();
        __syncthreads();
        uint32_t ah = sb + s * HW_STAGE;
        uint32_t al = ah + TILE_SZ;
        uint32_t bh = ah + 2 * TILE_SZ;
        uint32_t bl = ah + 3 * TILE_SZ;
#pragma unroll
        for (int kk = 0; kk < 2; kk++) {
            uint32_t ahr[2][4], alr[2][4], bhr[8][2], blr[8][2];
#pragma unroll
            for (int i = 0; i < 2; i++) {
                ldm_x4(ahr[i], ah + (arow + i * 16) * TSTRIDE + koff + kk * 32);
                ldm_x4(alr[i], al + (arow + i * 16) * TSTRIDE + koff + kk * 32);
            }
#pragma unroll
            for (int f = 0; f < 4; f++) {
                uint32_t t[4];
                ldm_x4(t, bh + (brow + f * 16) * TSTRIDE + koff + kk * 32);
                bhr[2 * f][0] = t[0]; bhr[2 * f][1] = t[2];
                bhr[2 * f + 1][0] = t[1]; bhr[2 * f + 1][1] = t[3];
                ldm_x4(t, bl + (brow + f * 16) * TSTRIDE + koff + kk * 32);
                blr[2 * f][0] = t[0]; blr[2 * f][1] = t[2];
                blr[2 * f + 1][0] = t[1]; blr[2 * f + 1][1] = t[3];
            }
#pragma unroll
            for (int i = 0; i < 2; i++)
#pragma unroll
                for (int j = 0; j < 8; j++) {
                    mma_bf16(acc[i][j], ahr[i], bhr[j][0], bhr[j][1]);
                    mma_bf16(acc[i][j], ahr[i], blr[j][0], blr[j][1]);
                    mma_bf16(acc[i][j], alr[i], bhr[j][0], bhr[j][1]);
                }
        }
        __syncthreads();
    }

    // stage C in smem [128][129] fp32
    float* cs = (float*)smem;
#pragma unroll
    for (int i = 0; i < 2; i++) {
        int ra = wm * 32 + i * 16 + (lane >> 2);
#pragma unroll
        for (int j = 0; j < 8; j++) {
            int col = wn * 64 + j * 8 + (lane & 3) * 2;
            cs[ra * 129 + col]           = acc[i][j][0];
            cs[ra * 129 + col + 1]       = acc[i][j][1];
            cs[(ra + 8) * 129 + col]     = acc[i][j][2];
            cs[(ra + 8) * 129 + col + 1] = acc[i][j][3];
        }
    }
    __syncthreads();

    int b = r0 >> 12, m0 = r0 & (NN - 1);
#pragma unroll 4
    for (int q = 0; q < 64; q++) {          // g_HW rows coalesced
        int idx = tid + q * 256;
        int r = idx >> 7, o = idx & 127;
        g_HW[(size_t)(r0 + r) * FD + o0 + o] = cs[r * 129 + o];
    }
#pragma unroll 4
    for (int q = 0; q < 64; q++) {          // g_Bt transposed, d_m-scaled
        int idx = tid + q * 256;
        int o = idx >> 7, m = idx & 127;
        float v = cs[m * 129 + o] * g_dinv[m0 + m];
        g_Bt[(size_t)(b * 256 + o0 + o) * NN + m0 + m] = __float2bfloat16(v);
    }
}

// ---------------- launch 4 (PROFILED): main GEMM ----------------------------
// 128(n) x 256(c) x 32 tiles, 512 threads (4x4 warps, 32x64 warp tiles),
// K=4096 (128 iters), 3-stage cp.async pipeline, cross-kk frag double-buffer.
static constexpr int MAIN_STAGE = TILE_SZ + BTILE_SZ;   // 30720
static constexpr int SMEM_MAIN  = 3 * MAIN_STAGE;       // 92160

__global__ __launch_bounds__(512, 1) void main_gemm_mma(float* __restrict__ out) {
    extern __shared__ char smem[];
    uint32_t sb = s2u(smem);
    int tid = threadIdx.x, lane = tid & 31, wid = tid >> 5;
    int wm = wid & 3, wn = wid >> 2;       // 4 x 4 warps
    int b  = blockIdx.x;                   // batch == column tile (256 cols)
    int n0 = blockIdx.y * 128;             // row block

    const char* Ag = (const char*)g_An + (size_t)n0 * (NN * 2);
    const char* Bg = (const char*)g_Bt + (size_t)b * 256 * (NN * 2);

    auto load = [&](int kt, int s) {
        uint32_t base = sb + s * MAIN_STAGE;
        size_t gk = (size_t)kt * 64;
        {
            int r = tid >> 2, c = tid & 3;
            CPA16(base + r * TSTRIDE + c * 16, Ag + (size_t)r * (NN * 2) + gk + c * 16);
        }
#pragma unroll
        for (int h = 0; h < 2; h++) {
            int id = tid + h * 512;
            int r = id >> 2, c = id & 3;
            CPA16(base + TILE_SZ + r * TSTRIDE + c * 16,
                  Bg + (size_t)r * (NN * 2) + gk + c * 16);
        }
        CPA_COMMIT();
    };

    float acc[2][8][4];
#pragma unroll
    for (int i = 0; i < 2; i++)
#pragma unroll
        for (int j = 0; j < 8; j++)
#pragma unroll
            for (int v = 0; v < 4; v++) acc[i][j][v] = 0.f;

    int grp = lane >> 3, lr = lane & 7;
    int arow = wm * 32 + (grp & 1) * 8 + lr;
    int brow = wn * 64 + (grp & 1) * 8 + lr;
    int koff = (grp >> 1) * 16;

    load(0, 0);
    load(1, 1);
    for (int kt = 0; kt < 128; kt++) {
        int s = kt % 3;
        CPA_WAIT1();
        __syncthreads();
        uint32_t ab = sb + s * MAIN_STAGE;
        uint32_t bb = ab + TILE_SZ;
        // issue ALL fragment loads for both k-halves first (latency overlap)
        uint32_t afr[2][2][4], bfr[2][8][2];
#pragma unroll
        for (int kk = 0; kk < 2; kk++) {
#pragma unroll
            for (int i = 0; i < 2; i++)
                ldm_x4(afr[kk][i], ab + (arow + i * 16) * TSTRIDE + koff + kk * 32);
#pragma unroll
            for (int f = 0; f < 4; f++) {
                uint32_t t[4];
                ldm_x4(t, bb + (brow + f * 16) * TSTRIDE + koff + kk * 32);
                bfr[kk][2 * f][0] = t[0]; bfr[kk][2 * f][1] = t[2];
                bfr[kk][2 * f + 1][0] = t[1]; bfr[kk][2 * f + 1][1] = t[3];
            }
        }
        if (kt + 2 < 128) load(kt + 2, (kt + 2) % 3);
#pragma unroll
        for (int kk = 0; kk < 2; kk++)
#pragma unroll
            for (int i = 0; i < 2; i++)
#pragma unroll
                for (int j = 0; j < 8; j++)
                    mma_bf16(acc[i][j], afr[kk][i], bfr[kk][j][0], bfr[kk][j][1]);
    }

    // epilogue: out = relu(HW - d_n * acc)
    const float* HWb = g_HW + (size_t)b * NN * FD;
    float* outb = out + (size_t)b * NN * FD;
#pragma unroll
    for (int i = 0; i < 2; i++) {
        int na = n0 + wm * 32 + i * 16 + (lane >> 2);
        int nb = na + 8;
        float dna = g_dinv[na], dnb = g_dinv[nb];
#pragma unroll
        for (int j = 0; j < 8; j++) {
            int o = wn * 64 + j * 8 + (lane & 3) * 2;
            float2 ha = *(const float2*)(HWb + (size_t)na * FD + o);
            float2 hb = *(const float2*)(HWb + (size_t)nb * FD + o);
            float2 oa, ob;
            oa.x = fmaxf(ha.x - dna * acc[i][j][0], 0.f);
            oa.y = fmaxf(ha.y - dna * acc[i][j][1], 0.f);
            ob.x = fmaxf(hb.x - dnb * acc[i][j][2], 0.f);
            ob.y = fmaxf(hb.y - dnb * acc[i][j][3], 0.f);
            *(float2*)(outb + (size_t)na * FD + o) = oa;
            *(float2*)(outb + (size_t)nb * FD + o) = ob;
        }
    }
}

// ---------------------------------------------------------------------------
extern "C" void kernel_launch(void* const* d_in, const int* in_sizes, int n_in,
                              void* d_out, int out_size) {
    const float* H = (const float*)d_in[0];  // [8, 4096, 256]
    const float* W = (const float*)d_in[1];  // [256, 256]
    const float* A = (const float*)d_in[2];  // [4096, 4096]
    float* out = (float*)d_out;              // [8, 4096, 256]

    cudaFuncSetAttribute(hw_gemm_mma, cudaFuncAttributeMaxDynamicSharedMemorySize, SMEM_HW);
    cudaFuncSetAttribute(main_gemm_mma, cudaFuncAttributeMaxDynamicSharedMemorySize, SMEM_MAIN);

    anorm_k<<<dim3(128, 128), dim3(32, 8)>>>(A);
    fused_prep<<<8272, 256>>>(H, W);
    hw_gemm_mma<<<dim3(FD / 128, (BB * NN) / 128), 256, SMEM_HW>>>();
    main_gemm_mma<<<dim3(BB, NN / 128), 512, SMEM_MAIN>>>(out);   // 4th: profiled
}

// round 9
// speedup vs baseline: 1.1459x; 1.1459x over previous
#include <cuda_runtime.h>
#include <cuda_bf16.h>
#include <cstdint>

#define NN 4096
#define FD 256
#define BB 8

// ---------------- scratch (__device__ globals; no allocs allowed) ----------
__device__ __nv_bfloat16 g_An[(size_t)NN * NN];          // 32MB relu(sym(A)) bf16
__device__ __nv_bfloat16 g_Bt[(size_t)BB * FD * NN];     // 16MB (d_m*HW)^T rows c=b*256+o
__device__ __nv_bfloat16 g_Hhi[(size_t)BB * NN * FD];    // 16MB H hi split
__device__ __nv_bfloat16 g_Hlo[(size_t)BB * NN * FD];    // 16MB H lo split
__device__ __nv_bfloat16 g_Wht[FD * FD];                 // W^T hi  [o][k]
__device__ __nv_bfloat16 g_Wlt[FD * FD];                 // W^T lo  [o][k]
__device__ float g_HW[(size_t)BB * NN * FD];             // 32MB H@W fp32
__device__ float g_dinv[NN];
__device__ float g_Dpart[(size_t)128 * NN];              // [bj][row] col-major partials

// ---------------- PTX helpers (sm_80-era only: cp.async/ldmatrix/mma) ------
__device__ __forceinline__ uint32_t s2u(const void* p) {
    uint32_t a;
    asm("{ .reg .u64 t; cvta.to.shared.u64 t, %1; cvt.u32.u64 %0, t; }" : "=r"(a) : "l"(p));
    return a;
}

#define CPA16(dst, src) \
    asm volatile("cp.async.cg.shared.global [%0], [%1], 16;\n" :: "r"(dst), "l"(src))
#define CPA_COMMIT() asm volatile("cp.async.commit_group;\n" ::: "memory")
#define CPA_WAIT0()  asm volatile("cp.async.wait_group 0;\n" ::: "memory")
#define CPA_WAIT1()  asm volatile("cp.async.wait_group 1;\n" ::: "memory")

__device__ __forceinline__ void ldm_x4(uint32_t (&r)[4], uint32_t addr) {
    asm volatile("ldmatrix.sync.aligned.m8n8.x4.shared.b16 {%0,%1,%2,%3}, [%4];"
                 : "=r"(r[0]), "=r"(r[1]), "=r"(r[2]), "=r"(r[3]) : "r"(addr));
}

__device__ __forceinline__ void mma_bf16(float (&c)[4], const uint32_t (&a)[4],
                                         uint32_t b0, uint32_t b1) {
    asm volatile(
        "mma.sync.aligned.m16n8k16.row.col.f32.bf16.bf16.f32 "
        "{%0,%1,%2,%3}, {%4,%5,%6,%7}, {%8,%9}, {%0,%1,%2,%3};"
        : "+f"(c[0]), "+f"(c[1]), "+f"(c[2]), "+f"(c[3])
        : "r"(a[0]), "r"(a[1]), "r"(a[2]), "r"(a[3]), "r"(b0), "r"(b1));
}

#define TSTRIDE 80
#define TILE_SZ (128 * TSTRIDE)    // 10240 B per 128x32 bf16 tile

// ---------------- launch 1: triangular anorm + partial row sums -------------
__global__ void anorm_k(const float* __restrict__ A) {
    int bj = blockIdx.x, bi = blockIdx.y;
    if (bj < bi) return;                    // upper-triangular blocks only
    __shared__ float tA[32][33], tB[32][33];
    int i0 = bi * 32, j0 = bj * 32;
    int tx = threadIdx.x, ty = threadIdx.y;  // 32 x 8
    for (int r = ty; r < 32; r += 8) {
        tA[r][tx] = A[(size_t)(i0 + r) * NN + j0 + tx];
        tB[r][tx] = A[(size_t)(j0 + r) * NN + i0 + tx];
    }
    __syncthreads();
    for (int r = ty; r < 32; r += 8) {
        float v = 0.5f * (tA[r][tx] + tB[tx][r]);
        v = v > 0.f ? v : 0.f;
        g_An[(size_t)(i0 + r) * NN + j0 + tx] = __float2bfloat16(v);
        float s = v;
#pragma unroll
        for (int o = 16; o; o >>= 1) s += __shfl_xor_sync(0xFFFFFFFFu, s, o);
        if (tx == 0) g_Dpart[(size_t)bj * NN + i0 + r] = s;
    }
    if (bi != bj) {
        for (int r = ty; r < 32; r += 8) {
            float v = 0.5f * (tB[r][tx] + tA[tx][r]);
            v = v > 0.f ? v : 0.f;
            g_An[(size_t)(j0 + r) * NN + i0 + tx] = __float2bfloat16(v);
            float s = v;
#pragma unroll
            for (int o = 16; o; o >>= 1) s += __shfl_xor_sync(0xFFFFFFFFu, s, o);
            if (tx == 0) g_Dpart[(size_t)bi * NN + j0 + r] = s;
        }
    }
}

// ---------------- launch 2: fused split_h + split_wt + dinv -----------------
__global__ void fused_prep(const float* __restrict__ H, const float* __restrict__ W) {
    int blk = blockIdx.x, tid = threadIdx.x;
    if (blk < 8192) {                        // --- H hi/lo split (float4) ---
        size_t i = ((size_t)blk * 256 + tid) * 4;
        float4 v = *(const float4*)(H + i);
        __nv_bfloat16 h0 = __float2bfloat16(v.x), h1 = __float2bfloat16(v.y);
        __nv_bfloat16 h2 = __float2bfloat16(v.z), h3 = __float2bfloat16(v.w);
        __nv_bfloat16 l0 = __float2bfloat16(v.x - __bfloat162float(h0));
        __nv_bfloat16 l1 = __float2bfloat16(v.y - __bfloat162float(h1));
        __nv_bfloat16 l2 = __float2bfloat16(v.z - __bfloat162float(h2));
        __nv_bfloat16 l3 = __float2bfloat16(v.w - __bfloat162float(h3));
        __nv_bfloat162* hi = (__nv_bfloat162*)(g_Hhi + i);
        __nv_bfloat162* lo = (__nv_bfloat162*)(g_Hlo + i);
        hi[0] = __nv_bfloat162(h0, h1); hi[1] = __nv_bfloat162(h2, h3);
        lo[0] = __nv_bfloat162(l0, l1); lo[1] = __nv_bfloat162(l2, l3);
    } else if (blk < 8256) {                 // --- W^T hi/lo split ---
        __shared__ float t[32][33];
        int tI = blk - 8192;
        int o0 = (tI & 7) * 32, k0 = (tI >> 3) * 32;
        for (int i = tid; i < 1024; i += 256) {
            int r = i >> 5, c = i & 31;
            t[r][c] = W[(size_t)(k0 + r) * FD + o0 + c];
        }
        __syncthreads();
        for (int i = tid; i < 1024; i += 256) {
            int r = i >> 5, c = i & 31;
            float v = t[c][r];               // W[k0+c][o0+r]
            __nv_bfloat16 hi = __float2bfloat16(v);
            size_t idx = (size_t)(o0 + r) * FD + k0 + c;
            g_Wht[idx] = hi;
            g_Wlt[idx] = __float2bfloat16(v - __bfloat162float(hi));
        }
    } else {                                 // --- dinv from partials ---
        int row = (blk - 8256) * 256 + tid;  // coalesced: g_Dpart[j][row]
        float s = 0.f;
#pragma unroll 8
        for (int j = 0; j < 128; j++) s += g_Dpart[(size_t)j * NN + row];
        g_dinv[row] = (s > 0.f) ? rsqrtf(s) : 0.f;
    }
}

// ---------------- launch 3: HW = H@W (3-pass bf16 split via mma.sync) -------
static constexpr int HW_STAGE = 4 * TILE_SZ;          // Ahi,Alo,Bhi,Blo
static constexpr int SMEM_HW  = 2 * HW_STAGE;         // 81920 (>= 128*129*4 epi)

__global__ __launch_bounds__(256, 1) void hw_gemm_mma() {
    extern __shared__ char smem[];
    uint32_t sb = s2u(smem);
    int tid = threadIdx.x, lane = tid & 31, wid = tid >> 5;
    int wm = wid >> 1, wn = wid & 1;
    int o0 = blockIdx.x * 128;
    int r0 = blockIdx.y * 128;

    const char* Ahg = (const char*)g_Hhi + (size_t)r0 * (FD * 2);
    const char* Alg = (const char*)g_Hlo + (size_t)r0 * (FD * 2);
    const char* Bhg = (const char*)g_Wht + (size_t)o0 * (FD * 2);
    const char* Blg = (const char*)g_Wlt + (size_t)o0 * (FD * 2);

    auto load = [&](int kt, int s) {
        uint32_t base = sb + s * HW_STAGE;
        size_t gk = (size_t)kt * 64;
#pragma unroll
        for (int h = 0; h < 2; h++) {
            int id = tid + h * 256;
            int r = id >> 2, c = id & 3;
            uint32_t so = r * TSTRIDE + c * 16;
            size_t go = (size_t)r * (FD * 2) + gk + c * 16;
            CPA16(base + so,               Ahg + go);
            CPA16(base + TILE_SZ + so,     Alg + go);
            CPA16(base + 2 * TILE_SZ + so, Bhg + go);
            CPA16(base + 3 * TILE_SZ + so, Blg + go);
        }
        CPA_COMMIT();
    };

    float acc[2][8][4];
#pragma unroll
    for (int i = 0; i < 2; i++)
#pragma unroll
        for (int j = 0; j < 8; j++)
#pragma unroll
            for (int v = 0; v < 4; v++) acc[i][j][v] = 0.f;

    int grp = lane >> 3, lr = lane & 7;
    int arow = wm * 32 + (grp & 1) * 8 + lr;
    int brow = wn * 64 + (grp & 1) * 8 + lr;
    int koff = (grp >> 1) * 16;

    load(0, 0);
    for (int kt = 0; kt < 8; kt++) {
        int s = kt & 1;
        if (kt + 1 < 8) { load(kt + 1, (kt + 1) & 1); CPA_WAIT1(); }
        else CPA_WAIT0();
        __syncthreads();
        uint32_t ah = sb + s * HW_STAGE;
        uint32_t al = ah + TILE_SZ;
        uint32_t bh = ah + 2 * TILE_SZ;
        uint32_t bl = ah + 3 * TILE_SZ;
#pragma unroll
        for (int kk = 0; kk < 2; kk++) {
            uint32_t ahr[2][4], alr[2][4], bhr[8][2], blr[8][2];
#pragma unroll
            for (int i = 0; i < 2; i++) {
                ldm_x4(ahr[i], ah + (arow + i * 16) * TSTRIDE + koff + kk * 32);
                ldm_x4(alr[i], al + (arow + i * 16) * TSTRIDE + koff + kk * 32);
            }
#pragma unroll
            for (int f = 0; f < 4; f++) {
                uint32_t t[4];
                ldm_x4(t, bh + (brow + f * 16) * TSTRIDE + koff + kk * 32);
                bhr[2 * f][0] = t[0]; bhr[2 * f][1] = t[2];
                bhr[2 * f + 1][0] = t[1]; bhr[2 * f + 1][1] = t[3];
                ldm_x4(t, bl + (brow + f * 16) * TSTRIDE + koff + kk * 32);
                blr[2 * f][0] = t[0]; blr[2 * f][1] = t[2];
                blr[2 * f + 1][0] = t[1]; blr[2 * f + 1][1] = t[3];
            }
#pragma unroll
            for (int i = 0; i < 2; i++)
#pragma unroll
                for (int j = 0; j < 8; j++) {
                    mma_bf16(acc[i][j], ahr[i], bhr[j][0], bhr[j][1]);
                    mma_bf16(acc[i][j], ahr[i], blr[j][0], blr[j][1]);
                    mma_bf16(acc[i][j], alr[i], bhr[j][0], bhr[j][1]);
                }
        }
        __syncthreads();
    }

    // stage C in smem [128][129] fp32
    float* cs = (float*)smem;
#pragma unroll
    for (int i = 0; i < 2; i++) {
        int ra = wm * 32 + i * 16 + (lane >> 2);
#pragma unroll
        for (int j = 0; j < 8; j++) {
            int col = wn * 64 + j * 8 + (lane & 3) * 2;
            cs[ra * 129 + col]           = acc[i][j][0];
            cs[ra * 129 + col + 1]       = acc[i][j][1];
            cs[(ra + 8) * 129 + col]     = acc[i][j][2];
            cs[(ra + 8) * 129 + col + 1] = acc[i][j][3];
        }
    }
    __syncthreads();

    int b = r0 >> 12, m0 = r0 & (NN - 1);
#pragma unroll 4
    for (int q = 0; q < 64; q++) {          // g_HW rows coalesced
        int idx = tid + q * 256;
        int r = idx >> 7, o = idx & 127;
        g_HW[(size_t)(r0 + r) * FD + o0 + o] = cs[r * 129 + o];
    }
#pragma unroll 4
    for (int q = 0; q < 64; q++) {          // g_Bt transposed, d_m-scaled
        int idx = tid + q * 256;
        int o = idx >> 7, m = idx & 127;
        float v = cs[m * 129 + o] * g_dinv[m0 + m];
        g_Bt[(size_t)(b * 256 + o0 + o) * NN + m0 + m] = __float2bfloat16(v);
    }
}

// ---------------- launch 4 (PROFILED): main GEMM ----------------------------
// 128x128x32 tiles, 256 threads (4m x 2n warps, 32x64 warp tiles), 3-stage,
// TWO CTAs per SM so barrier phases stagger (LDSM of one overlaps MMA of other).
static constexpr int MAIN_STAGE = 2 * TILE_SZ;         // 20480
static constexpr int SMEM_MAIN  = 3 * MAIN_STAGE;      // 61440 (x2 CTA = 122880)

__global__ __launch_bounds__(256, 2) void main_gemm_mma(float* __restrict__ out) {
    extern __shared__ char smem[];
    uint32_t sb = s2u(smem);
    int tid = threadIdx.x, lane = tid & 31, wid = tid >> 5;
    int wm = wid >> 1, wn = wid & 1;       // 4 x 2 warps
    int c0 = blockIdx.x * 128;             // global col (c = b*256 + o)
    int n0 = blockIdx.y * 128;             // row block

    const char* Ag = (const char*)g_An + (size_t)n0 * (NN * 2);
    const char* Bg = (const char*)g_Bt + (size_t)c0 * (NN * 2);

    auto load = [&](int kt, int s) {
        uint32_t base = sb + s * MAIN_STAGE;
        size_t gk = (size_t)kt * 64;
#pragma unroll
        for (int h = 0; h < 2; h++) {
            int id = tid + h * 256;
            int r = id >> 2, c = id & 3;
            uint32_t so = r * TSTRIDE + c * 16;
            size_t go = (size_t)r * (NN * 2) + gk + c * 16;
            CPA16(base + so,           Ag + go);
            CPA16(base + TILE_SZ + so, Bg + go);
        }
        CPA_COMMIT();
    };

    float acc[2][8][4];
#pragma unroll
    for (int i = 0; i < 2; i++)
#pragma unroll
        for (int j = 0; j < 8; j++)
#pragma unroll
            for (int v = 0; v < 4; v++) acc[i][j][v] = 0.f;

    int grp = lane >> 3, lr = lane & 7;
    int arow = wm * 32 + (grp & 1) * 8 + lr;
    int brow = wn * 64 + (grp & 1) * 8 + lr;
    int koff = (grp >> 1) * 16;

    load(0, 0);
    load(1, 1);
    for (int kt = 0; kt < 128; kt++) {
        int s = kt % 3;
        CPA_WAIT1();
        __syncthreads();
        if (kt + 2 < 128) load(kt + 2, (kt + 2) % 3);
        uint32_t ab = sb + s * MAIN_STAGE;
        uint32_t bb = ab + TILE_SZ;
#pragma unroll
        for (int kk = 0; kk < 2; kk++) {
            uint32_t a[2][4], bfr[8][2];
#pragma unroll
            for (int i = 0; i < 2; i++)
                ldm_x4(a[i], ab + (arow + i * 16) * TSTRIDE + koff + kk * 32);
#pragma unroll
            for (int f = 0; f < 4; f++) {
                uint32_t t[4];
                ldm_x4(t, bb + (brow + f * 16) * TSTRIDE + koff + kk * 32);
                bfr[2 * f][0] = t[0]; bfr[2 * f][1] = t[2];
                bfr[2 * f + 1][0] = t[1]; bfr[2 * f + 1][1] = t[3];
            }
#pragma unroll
            for (int i = 0; i < 2; i++)
#pragma unroll
                for (int j = 0; j < 8; j++)
                    mma_bf16(acc[i][j], a[i], bfr[j][0], bfr[j][1]);
        }
    }

    // epilogue: out = relu(HW - d_n * acc)
    int b = c0 >> 8, obase = c0 & 255;
    const float* HWb = g_HW + (size_t)b * NN * FD;
    float* outb = out + (size_t)b * NN * FD;
#pragma unroll
    for (int i = 0; i < 2; i++) {
        int na = n0 + wm * 32 + i * 16 + (lane >> 2);
        int nb = na + 8;
        float dna = g_dinv[na], dnb = g_dinv[nb];
#pragma unroll
        for (int j = 0; j < 8; j++) {
            int o = obase + wn * 64 + j * 8 + (lane & 3) * 2;
            float2 ha = *(const float2*)(HWb + (size_t)na * FD + o);
            float2 hb = *(const float2*)(HWb + (size_t)nb * FD + o);
            float2 oa, ob;
            oa.x = fmaxf(ha.x - dna * acc[i][j][0], 0.f);
            oa.y = fmaxf(ha.y - dna * acc[i][j][1], 0.f);
            ob.x = fmaxf(hb.x - dnb * acc[i][j][2], 0.f);
            ob.y = fmaxf(hb.y - dnb * acc[i][j][3], 0.f);
            *(float2*)(outb + (size_t)na * FD + o) = oa;
            *(float2*)(outb + (size_t)nb * FD + o) = ob;
        }
    }
}

// ---------------------------------------------------------------------------
extern "C" void kernel_launch(void* const* d_in, const int* in_sizes, int n_in,
                              void* d_out, int out_size) {
    const float* H = (const float*)d_in[0];  // [8, 4096, 256]
    const float* W = (const float*)d_in[1];  // [256, 256]
    const float* A = (const float*)d_in[2];  // [4096, 4096]
    float* out = (float*)d_out;              // [8, 4096, 256]

    cudaFuncSetAttribute(hw_gemm_mma, cudaFuncAttributeMaxDynamicSharedMemorySize, SMEM_HW);
    cudaFuncSetAttribute(main_gemm_mma, cudaFuncAttributeMaxDynamicSharedMemorySize, SMEM_MAIN);

    anorm_k<<<dim3(128, 128), dim3(32, 8)>>>(A);
    fused_prep<<<8272, 256>>>(H, W);
    hw_gemm_mma<<<dim3(FD / 128, (BB * NN) / 128), 256, SMEM_HW>>>();
    main_gemm_mma<<<dim3((BB * FD) / 128, NN / 128), 256, SMEM_MAIN>>>(out);  // 4th: profiled
}